// round 14
// baseline (speedup 1.0000x reference)
#include <cuda_runtime.h>
#include <cuda_fp16.h>
#include <math.h>
#include <cstdint>

#define D_MODEL 1024
#define N_HEADS 16
#define D_K     64
#define BATCH   2
#define SEQ     2048
#define M_ROWS  (BATCH * SEQ)   /* 4096 */
/* Q pre-scale: 1/sqrt(64) * log2(e), baked into gemm1 epilogue for q columns */
#define QFAC    0.1803368801111f

// ---------------------------------------------------------------------------
// Scratch (allocation-free rule: __device__ globals)
// ---------------------------------------------------------------------------
__device__ __half g_A16[(size_t)M_ROWS * D_MODEL];
__device__ __half g_ctx16[(size_t)M_ROWS * D_MODEL];
__device__ __half g_QKV[(size_t)M_ROWS * 3 * D_MODEL];
__device__ __half g_W1[(size_t)3 * D_MODEL * D_MODEL];   // w_qkv^T [3072,1024]
__device__ __half g_W2[(size_t)D_MODEL * D_MODEL];       // w_o^T [1024,1024]

// ---------------------------------------------------------------------------
// Helpers
// ---------------------------------------------------------------------------
__device__ __forceinline__ uint32_t smem_u32(const void* p) {
    uint32_t a;
    asm("{ .reg .u64 t; cvta.to.shared.u64 t, %1; cvt.u32.u64 %0, t; }"
        : "=r"(a) : "l"(p));
    return a;
}
__device__ __forceinline__ float ex2f(float x) {
    float y;
    asm("ex2.approx.f32 %0, %1;" : "=f"(y) : "f"(x));
    return y;
}
// packed half2 exp2: one SFU op for two values
__device__ __forceinline__ uint32_t h2ex2(uint32_t x) {
    uint32_t y;
    asm("ex2.approx.f16x2 %0, %1;" : "=r"(y) : "r"(x));
    return y;
}
__device__ __forceinline__ uint32_t h2max(uint32_t a, uint32_t b) {
    uint32_t y;
    asm("max.f16x2 %0, %1, %2;" : "=r"(y) : "r"(a), "r"(b));
    return y;
}

#define CP_ASYNC16(saddr, gptr) \
    asm volatile("cp.async.cg.shared.global [%0], [%1], 16;" :: "r"(saddr), "l"(gptr))
#define CP_COMMIT() asm volatile("cp.async.commit_group;")
#define CP_WAIT2()  asm volatile("cp.async.wait_group 2;")
#define CP_WAIT1()  asm volatile("cp.async.wait_group 1;")
#define CP_WAIT0()  asm volatile("cp.async.wait_group 0;")

#define LDSM4(r, addr) \
    asm volatile("ldmatrix.sync.aligned.m8n8.x4.shared.b16 {%0,%1,%2,%3}, [%4];" \
        : "=r"((r)[0]), "=r"((r)[1]), "=r"((r)[2]), "=r"((r)[3]) : "r"(addr))
#define LDSM4T(r, addr) \
    asm volatile("ldmatrix.sync.aligned.m8n8.x4.trans.shared.b16 {%0,%1,%2,%3}, [%4];" \
        : "=r"((r)[0]), "=r"((r)[1]), "=r"((r)[2]), "=r"((r)[3]) : "r"(addr))

#define MMA16816(d, a, b0, b1) \
    asm volatile("mma.sync.aligned.m16n8k16.row.col.f32.f16.f16.f32 " \
        "{%0,%1,%2,%3}, {%4,%5,%6,%7}, {%8,%9}, {%0,%1,%2,%3};" \
        : "+f"((d)[0]), "+f"((d)[1]), "+f"((d)[2]), "+f"((d)[3]) \
        : "r"((a)[0]), "r"((a)[1]), "r"((a)[2]), "r"((a)[3]), "r"(b0), "r"(b1))

/* C = 0 variant (no accumulator read) */
#define MMA16816_INIT(d, a, b0, b1) \
    asm volatile("mma.sync.aligned.m16n8k16.row.col.f32.f16.f16.f32 " \
        "{%0,%1,%2,%3}, {%4,%5,%6,%7}, {%8,%9}, {%10,%10,%10,%10};" \
        : "=f"((d)[0]), "=f"((d)[1]), "=f"((d)[2]), "=f"((d)[3]) \
        : "r"((a)[0]), "r"((a)[1]), "r"((a)[2]), "r"((a)[3]), "r"(b0), "r"(b1), \
          "f"(0.f))

__device__ __forceinline__ uint32_t packh2(float x, float y) {
    __half2 h = __floats2half2_rn(x, y);
    return *(uint32_t*)&h;
}

// ---------------------------------------------------------------------------
// Fused prep kernel (one launch): W1^T, W2^T transpose-convert + query->fp16.
// ---------------------------------------------------------------------------
__global__ void prep_kernel(const float* __restrict__ query,
                            const float* __restrict__ w_qkv,
                            const float* __restrict__ w_o,
                            __half* __restrict__ A16,
                            __half* __restrict__ W1,
                            __half* __restrict__ W2)
{
    const int bid = blockIdx.x;
    const int tx = threadIdx.x, ty = threadIdx.y;

    if (bid < 4096) {
        const float* W;
        __half* T;
        int N, nb, b;
        if (bid < 3072) { W = w_qkv; T = W1; N = 3 * D_MODEL; nb = 96; b = bid; }
        else            { W = w_o;   T = W2; N = D_MODEL;     nb = 32; b = bid - 3072; }
        const int K = D_MODEL;
        const int n0 = (b % nb) * 32;
        const int k0 = (b / nb) * 32;
        __shared__ float t[32][33];
        #pragma unroll
        for (int i = ty; i < 32; i += 8)
            t[i][tx] = W[(size_t)(k0 + i) * N + n0 + tx];
        __syncthreads();
        #pragma unroll
        for (int i = ty; i < 32; i += 8)
            T[(size_t)(n0 + i) * K + k0 + tx] = __float2half_rn(t[tx][i]);
    } else {
        int i = (bid - 4096) * 256 + ty * 32 + tx;
        float4 v = ((const float4*)query)[i];
        *(uint2*)(A16 + (size_t)i * 4) =
            make_uint2(packh2(v.x, v.y), packh2(v.z, v.w));
    }
}

// ---------------------------------------------------------------------------
// HMMA fp16 GEMM (R10 config): C = A16[M,K] @ W[N,K]^T
// CTA 128x128, BK=64, 8 warps (2m x 4n), 3-stage cp.async, single barrier.
// ---------------------------------------------------------------------------
#define G_TILE   16384
#define G_STAGE  (2 * G_TILE)        /* 32768 */
#define GEMM_SMEM (3 * G_STAGE)      /* 98304 */

__device__ __forceinline__ void gemm_load(
    const __half* __restrict__ A, const __half* __restrict__ B,
    uint32_t sb, int m0, int n0, int K, int kofs, int tid)
{
    const int cr = tid >> 3;
    const int cc = tid & 7;
    const uint32_t csw = (uint32_t)((cc ^ (cr & 7)) << 4);
    #pragma unroll
    for (int u = 0; u < 4; u++) {
        int r = cr + u * 32;
        uint32_t so = (uint32_t)(r * 128) + csw;
        CP_ASYNC16(sb + so,          A + (size_t)(m0 + r) * K + kofs + cc * 8);
        CP_ASYNC16(sb + G_TILE + so, B + (size_t)(n0 + r) * K + kofs + cc * 8);
    }
    CP_COMMIT();
}

template <bool HALF_OUT>
__global__ void __launch_bounds__(256, 2) gemm_hmma_kernel(
    const __half* __restrict__ A16, const __half* __restrict__ B16,
    float* __restrict__ C, __half* __restrict__ Ch,
    int M, int N, int K)
{
    extern __shared__ char smem[];
    const uint32_t sbase = smem_u32(smem);
    const int tid = threadIdx.x;
    const int lid = tid & 31;
    const int wid = tid >> 5;
    const int wm  = wid >> 2;
    const int wn  = wid & 3;
    const int m0 = blockIdx.y * 128;
    const int n0 = blockIdx.x * 128;

    const int niter = K / 64;

    gemm_load(A16, B16, sbase,           m0, n0, K, 0,  tid);
    gemm_load(A16, B16, sbase + G_STAGE, m0, n0, K, 64, tid);

    float acc[4][4][4];
    #pragma unroll
    for (int i = 0; i < 4; i++)
        #pragma unroll
        for (int j = 0; j < 4; j++)
            #pragma unroll
            for (int k = 0; k < 4; k++) acc[i][j][k] = 0.f;

    const int a_rowlane = lid & 15;
    const int a_csel    = lid >> 4;
    const int b_rowlane = ((lid >> 4) << 3) + (lid & 7);
    const int b_csel    = (lid >> 3) & 1;
    const int sw_lane   = lid & 7;

    int stage = 0;
    for (int kt = 0; kt < niter; kt++) {
        if (kt + 1 < niter) { CP_WAIT1(); } else { CP_WAIT0(); }
        __syncthreads();   // data visible AND all warps done reading stage kt-1

        if (kt + 2 < niter) {
            int ps = stage + 2; if (ps >= 3) ps -= 3;
            gemm_load(A16, B16, sbase + ps * G_STAGE, m0, n0, K, (kt + 2) * 64, tid);
        } else {
            CP_COMMIT();
        }

        const uint32_t sb = sbase + stage * G_STAGE;
        const uint32_t abase0 = sb + (uint32_t)((wm * 64 + a_rowlane) * 128);
        const uint32_t bbase0 = sb + G_TILE + (uint32_t)((wn * 32 + b_rowlane) * 128);

        #pragma unroll
        for (int ks = 0; ks < 4; ks++) {
            const uint32_t abase = abase0 + (uint32_t)(((ks * 2 + a_csel) ^ sw_lane) << 4);
            const uint32_t bbase = bbase0 + (uint32_t)(((ks * 2 + b_csel) ^ sw_lane) << 4);

            uint32_t a[4][4], bb[2][4];
            #pragma unroll
            for (int tm = 0; tm < 4; tm++) LDSM4(a[tm], abase + tm * 2048);
            #pragma unroll
            for (int tg = 0; tg < 2; tg++) LDSM4(bb[tg], bbase + tg * 2048);

            #pragma unroll
            for (int tm = 0; tm < 4; tm++) {
                #pragma unroll
                for (int tg = 0; tg < 2; tg++) {
                    MMA16816(acc[tm][tg * 2 + 0], a[tm], bb[tg][0], bb[tg][1]);
                    MMA16816(acc[tm][tg * 2 + 1], a[tm], bb[tg][2], bb[tg][3]);
                }
            }
        }
        if (++stage == 3) stage = 0;
    }

    const int erow = (lid >> 2);
    const int ecol = (lid & 3) * 2;
    #pragma unroll
    for (int tm = 0; tm < 4; tm++) {
        #pragma unroll
        for (int tg = 0; tg < 4; tg++) {
            int row = m0 + wm * 64 + tm * 16 + erow;
            int col = n0 + wn * 32 + tg * 8 + ecol;
            if (HALF_OUT) {
                float f = (col < D_MODEL) ? QFAC : 1.f;  // bake SCALE*log2e into q
                *(uint32_t*)(Ch + (size_t)row * N + col) =
                    packh2(acc[tm][tg][0] * f, acc[tm][tg][1] * f);
                *(uint32_t*)(Ch + (size_t)(row + 8) * N + col) =
                    packh2(acc[tm][tg][2] * f, acc[tm][tg][3] * f);
            } else {
                *(float2*)(C + (size_t)row * N + col) =
                    make_float2(acc[tm][tg][0], acc[tm][tg][1]);
                *(float2*)(C + (size_t)(row + 8) * N + col) =
                    make_float2(acc[tm][tg][2], acc[tm][tg][3]);
            }
        }
    }
}

// ---------------------------------------------------------------------------
// HMMA flash attention (causal), fp16. Loop order: softmax(kt) -> PV(kt)
// (pre-barrier: PV absorbs barrier skew) -> wait/sync -> prefetch ->
// QK(kt+1). Softmax chain: f16x2 packed max-shuffles, fused f16x2 exp2,
// ones-MMA row sums. 128 q-rows/CTA, 8 warps x m16, 4-stage KV ring.
// Q pre-scaled (log2 domain).
// ---------------------------------------------------------------------------
#define AQ    0
#define AKV0  (128 * 144)               /* 18432 */
#define KV_STAGE (2 * 64 * 144)         /* 18432 */
#define A_V   (64 * 144)
#define ATTN_SMEM (AKV0 + 4 * KV_STAGE) /* 92160 */

__device__ __forceinline__ void attn_load_kv(
    const __half* __restrict__ qkv, uint32_t dst, int grow0, int kcol, int tid)
{
    #pragma unroll
    for (int u = 0; u < 4; u++) {
        int piece = u >> 1;                       // 0:K 1:V
        int r = (u & 1) * 32 + (tid >> 3);
        int c = tid & 7;
        const __half* g = qkv + (size_t)(grow0 + r) * 3072 + kcol + piece * D_MODEL + c * 8;
        CP_ASYNC16(dst + piece * A_V + r * 144 + c * 16, g);
    }
    CP_COMMIT();
}

__global__ void __launch_bounds__(256, 2) attn_hmma_kernel(
    const __half* __restrict__ qkv, __half* __restrict__ ctx16)
{
    extern __shared__ char smem[];
    const uint32_t sbase = smem_u32(smem);
    const int tid = threadIdx.x;
    const int lid = tid & 31;
    const int wm  = tid >> 5;      // 0..7, warp covers rows wm*16..wm*16+15

    const int qb = (int)gridDim.x - 1 - (int)blockIdx.x;  // big tiles first
    const int bh = blockIdx.y;
    const int b  = bh >> 4;
    const int h  = bh & 15;
    const int q0 = qb * 128;
    const int nkt = qb * 2 + 2;    // >= 2

    const int qcol = h * D_K;
    const int browQ = b * SEQ + q0;
    const int kcol = D_MODEL + qcol;

    // --- Q loads (G0)
    #pragma unroll
    for (int u = 0; u < 4; u++) {
        int r = u * 32 + (tid >> 3);
        int c = tid & 7;
        CP_ASYNC16(sbase + AQ + r * 144 + c * 16,
                   qkv + (size_t)(browQ + r) * 3072 + qcol + c * 8);
    }
    CP_COMMIT();
    // --- KV tiles 0,1 (G1,G2); KV2 (G3, or empty commit)
    attn_load_kv(qkv, sbase + AKV0,            b * SEQ,      kcol, tid);
    attn_load_kv(qkv, sbase + AKV0 + KV_STAGE, b * SEQ + 64, kcol, tid);
    if (nkt > 2) {
        attn_load_kv(qkv, sbase + AKV0 + 2 * KV_STAGE, b * SEQ + 128, kcol, tid);
    } else {
        CP_COMMIT();
    }

    CP_WAIT2();            // Q + KV0 ready
    __syncthreads();

    // preload Q A-fragments (4 k-steps)
    const uint32_t q_addr = sbase + AQ + (uint32_t)((wm * 16 + (lid & 15)) * 144)
                            + (uint32_t)((lid >> 4) * 16);
    uint32_t aQ[4][4];
    #pragma unroll
    for (int ks = 0; ks < 4; ks++) LDSM4(aQ[ks], q_addr + ks * 32);

    const int b_row = ((lid >> 4) << 3) + (lid & 7);
    const int b_cs  = (lid >> 3) & 1;
    const int v_row = ((lid >> 3) & 1) * 8 + (lid & 7);
    const int v_col = (lid >> 4) * 8;
    const uint32_t ONES2 = 0x3C003C00u;   // half2(1,1)

    float O[8][4];
    #pragma unroll
    for (int t = 0; t < 8; t++)
        #pragma unroll
        for (int k = 0; k < 4; k++) O[t][k] = 0.f;
    float m0r = -1e30f, m1r = -1e30f, l0r = 0.f, l1r = 0.f;

    // ---- prologue: S(0) = QK(0)
    float S[8][4];
    #pragma unroll
    for (int t = 0; t < 8; t++)
        #pragma unroll
        for (int k = 0; k < 4; k++) S[t][k] = 0.f;
    {
        const uint32_t stg = sbase + AKV0;
        #pragma unroll
        for (int ks = 0; ks < 4; ks++) {
            const uint32_t kof = (uint32_t)((ks * 2 + b_cs) * 16);
            #pragma unroll
            for (int g = 0; g < 4; g++) {
                uint32_t kh[4];
                LDSM4(kh, stg + (uint32_t)((g * 16 + b_row) * 144) + kof);
                MMA16816(S[2 * g + 0], aQ[ks], kh[0], kh[1]);
                MMA16816(S[2 * g + 1], aQ[ks], kh[2], kh[3]);
            }
        }
    }

    const int row0 = q0 + wm * 16 + (lid >> 2);
    const int row1 = row0 + 8;
    const int wtop = q0 + wm * 16 + 15;   // highest q row in this warp

    for (int kt = 0; kt < nkt; kt++) {
        const int ktbase = kt * 64;
        const bool act_cur = (wtop >= ktbase);   // warp has any unmasked key

        if (act_cur) {
            // ---- softmax on S(kt) (log2 domain)
            const bool need_mask = (ktbase + 63) > row0;
            float vmax0 = -1e30f, vmax1 = -1e30f;
            #pragma unroll
            for (int t = 0; t < 8; t++) {
                float s0 = S[t][0], s1 = S[t][1], s2 = S[t][2], s3 = S[t][3];
                if (need_mask) {
                    int c0 = ktbase + t * 8 + (lid & 3) * 2;
                    if (c0     > row0) s0 = -1e9f;
                    if (c0 + 1 > row0) s1 = -1e9f;
                    if (c0     > row1) s2 = -1e9f;
                    if (c0 + 1 > row1) s3 = -1e9f;
                    S[t][0] = s0; S[t][1] = s1; S[t][2] = s2; S[t][3] = s3;
                }
                vmax0 = fmaxf(vmax0, fmaxf(s0, s1));
                vmax1 = fmaxf(vmax1, fmaxf(s2, s3));
            }
            // packed f16x2 max reduction (2 shuffles instead of 4)
            uint32_t vm = packh2(fmaxf(vmax0, -60000.f), fmaxf(vmax1, -60000.f));
            vm = h2max(vm, __shfl_xor_sync(0xffffffffu, vm, 1));
            vm = h2max(vm, __shfl_xor_sync(0xffffffffu, vm, 2));
            __half2 vmh = *(__half2*)&vm;
            const float mn0 = fmaxf(m0r, __low2float(vmh));
            const float mn1 = fmaxf(m1r, __high2float(vmh));
            const float a0 = ex2f(m0r - mn0);
            const float a1 = ex2f(m1r - mn1);
            m0r = mn0; m1r = mn1;

            // fused sub -> pack -> packed exp2 (output IS the P fragment)
            uint32_t aP[4][4];
            #pragma unroll
            for (int ks = 0; ks < 4; ks++) {
                aP[ks][0] = h2ex2(packh2(S[2 * ks][0] - mn0,     S[2 * ks][1] - mn0));
                aP[ks][1] = h2ex2(packh2(S[2 * ks][2] - mn1,     S[2 * ks][3] - mn1));
                aP[ks][2] = h2ex2(packh2(S[2 * ks + 1][0] - mn0, S[2 * ks + 1][1] - mn0));
                aP[ks][3] = h2ex2(packh2(S[2 * ks + 1][2] - mn1, S[2 * ks + 1][3] - mn1));
            }

            // row sums via ones-MMA
            float ls[4];
            MMA16816_INIT(ls, aP[0], ONES2, ONES2);
            MMA16816(ls, aP[1], ONES2, ONES2);
            MMA16816(ls, aP[2], ONES2, ONES2);
            MMA16816(ls, aP[3], ONES2, ONES2);
            l0r = l0r * a0 + ls[0];
            l1r = l1r * a1 + ls[2];

            #pragma unroll
            for (int t = 0; t < 8; t++) {
                O[t][0] *= a0; O[t][1] *= a0;
                O[t][2] *= a1; O[t][3] *= a1;
            }

            // ---- PV(kt) -> O BEFORE the barrier (absorbs barrier skew)
            const uint32_t stg = sbase + AKV0 + (kt & 3) * KV_STAGE;
            #pragma unroll
            for (int ks = 0; ks < 4; ks++) {
                #pragma unroll
                for (int g = 0; g < 4; g++) {
                    uint32_t vh[4];
                    LDSM4T(vh, stg + A_V + (uint32_t)((ks * 16 + v_row) * 144)
                               + (uint32_t)((v_col + g * 16) * 2));
                    MMA16816(O[2 * g + 0], aP[ks], vh[0], vh[1]);
                    MMA16816(O[2 * g + 1], aP[ks], vh[2], vh[3]);
                }
            }
        }

        const bool more = (kt + 1 < nkt);
        if (more) CP_WAIT1();        // KV(kt+1) resident
        __syncthreads();             // all warps done reading V(kt)/K stage kt-1

        // prefetch KV(kt+3) into stage (kt+3)&3 (last read two syncs ago)
        if (kt + 3 < nkt) {
            attn_load_kv(qkv, sbase + AKV0 + ((kt + 3) & 3) * KV_STAGE,
                         b * SEQ + (kt + 3) * 64, kcol, tid);
        } else {
            CP_COMMIT();
        }

        // ---- QK(kt+1) -> S (skip if warp fully masked at kt+1)
        if (more && (wtop >= (kt + 1) * 64)) {
            #pragma unroll
            for (int t = 0; t < 8; t++)
                #pragma unroll
                for (int k = 0; k < 4; k++) S[t][k] = 0.f;
            const uint32_t stgn = sbase + AKV0 + ((kt + 1) & 3) * KV_STAGE;
            #pragma unroll
            for (int ks = 0; ks < 4; ks++) {
                const uint32_t kof = (uint32_t)((ks * 2 + b_cs) * 16);
                #pragma unroll
                for (int g = 0; g < 4; g++) {
                    uint32_t kh[4];
                    LDSM4(kh, stgn + (uint32_t)((g * 16 + b_row) * 144) + kof);
                    MMA16816(S[2 * g + 0], aQ[ks], kh[0], kh[1]);
                    MMA16816(S[2 * g + 1], aQ[ks], kh[2], kh[3]);
                }
            }
        }
    }

    // ---- epilogue: normalize, fp16 pack, store ctx16 [4096,1024]
    const float inv0 = 1.f / l0r;
    const float inv1 = 1.f / l1r;
    const int gr0 = b * SEQ + row0;
    const int gr1 = b * SEQ + row1;
    #pragma unroll
    for (int t = 0; t < 8; t++) {
        int col = qcol + t * 8 + (lid & 3) * 2;
        *(uint32_t*)(ctx16 + (size_t)gr0 * D_MODEL + col) =
            packh2(O[t][0] * inv0, O[t][1] * inv0);
        *(uint32_t*)(ctx16 + (size_t)gr1 * D_MODEL + col) =
            packh2(O[t][2] * inv1, O[t][3] * inv1);
    }
}

// ---------------------------------------------------------------------------
extern "C" void kernel_launch(void* const* d_in, const int* in_sizes, int n_in,
                              void* d_out, int out_size)
{
    const float* query = (const float*)d_in[0];
    const float* w_qkv = (const float*)d_in[4];
    const float* w_o   = (const float*)d_in[5];
    float* out = (float*)d_out;

    __half *A16, *ctx16, *QKV, *W1, *W2;
    cudaGetSymbolAddress((void**)&A16,   g_A16);
    cudaGetSymbolAddress((void**)&ctx16, g_ctx16);
    cudaGetSymbolAddress((void**)&QKV,   g_QKV);
    cudaGetSymbolAddress((void**)&W1,    g_W1);
    cudaGetSymbolAddress((void**)&W2,    g_W2);

    cudaFuncSetAttribute(gemm_hmma_kernel<true>,
                         cudaFuncAttributeMaxDynamicSharedMemorySize, GEMM_SMEM);
    cudaFuncSetAttribute(gemm_hmma_kernel<false>,
                         cudaFuncAttributeMaxDynamicSharedMemorySize, GEMM_SMEM);
    cudaFuncSetAttribute(attn_hmma_kernel,
                         cudaFuncAttributeMaxDynamicSharedMemorySize, ATTN_SMEM);

    // 0) fused prep: W1^T, W2^T, query->fp16 in one launch
    prep_kernel<<<8192, dim3(32, 8)>>>(query, w_qkv, w_o, A16, W1, W2);

    // 1) qkv = query @ w_qkv -> fp16 (q columns pre-scaled by SCALE*log2e)
    gemm_hmma_kernel<true><<<dim3(3 * D_MODEL / 128, M_ROWS / 128), 256, GEMM_SMEM>>>(
        A16, W1, nullptr, QKV, M_ROWS, 3 * D_MODEL, D_MODEL);

    // 2) causal flash attention -> ctx fp16
    attn_hmma_kernel<<<dim3(SEQ / 128, BATCH * N_HEADS), 256, ATTN_SMEM>>>(
        QKV, ctx16);

    // 3) out = ctx @ w_o -> fp32
    gemm_hmma_kernel<false><<<dim3(D_MODEL / 128, M_ROWS / 128), 256, GEMM_SMEM>>>(
        ctx16, W2, out, nullptr, M_ROWS, D_MODEL, D_MODEL);
}

// round 15
// speedup vs baseline: 1.1712x; 1.1712x over previous
#include <cuda_runtime.h>
#include <cuda_fp16.h>
#include <math.h>
#include <cstdint>

#define D_MODEL 1024
#define N_HEADS 16
#define D_K     64
#define BATCH   2
#define SEQ     2048
#define M_ROWS  (BATCH * SEQ)   /* 4096 */
/* Q pre-scale: 1/sqrt(64) * log2(e), baked into gemm1 epilogue for q columns */
#define QFAC    0.1803368801111f

// ---------------------------------------------------------------------------
// Scratch (allocation-free rule: __device__ globals)
// ---------------------------------------------------------------------------
__device__ __half g_A16[(size_t)M_ROWS * D_MODEL];
__device__ __half g_ctx16[(size_t)M_ROWS * D_MODEL];
__device__ __half g_QKV[(size_t)M_ROWS * 3 * D_MODEL];
__device__ __half g_W1[(size_t)3 * D_MODEL * D_MODEL];   // w_qkv^T [3072,1024]
__device__ __half g_W2[(size_t)D_MODEL * D_MODEL];       // w_o^T [1024,1024]

// ---------------------------------------------------------------------------
// Helpers
// ---------------------------------------------------------------------------
__device__ __forceinline__ uint32_t smem_u32(const void* p) {
    uint32_t a;
    asm("{ .reg .u64 t; cvta.to.shared.u64 t, %1; cvt.u32.u64 %0, t; }"
        : "=r"(a) : "l"(p));
    return a;
}
__device__ __forceinline__ float ex2f(float x) {
    float y;
    asm("ex2.approx.f32 %0, %1;" : "=f"(y) : "f"(x));
    return y;
}
// packed half2 exp2: one SFU op for two values
__device__ __forceinline__ uint32_t h2ex2(uint32_t x) {
    uint32_t y;
    asm("ex2.approx.f16x2 %0, %1;" : "=r"(y) : "r"(x));
    return y;
}

#define CP_ASYNC16(saddr, gptr) \
    asm volatile("cp.async.cg.shared.global [%0], [%1], 16;" :: "r"(saddr), "l"(gptr))
#define CP_COMMIT() asm volatile("cp.async.commit_group;")
#define CP_WAIT2()  asm volatile("cp.async.wait_group 2;")
#define CP_WAIT1()  asm volatile("cp.async.wait_group 1;")
#define CP_WAIT0()  asm volatile("cp.async.wait_group 0;")

#define LDSM4(r, addr) \
    asm volatile("ldmatrix.sync.aligned.m8n8.x4.shared.b16 {%0,%1,%2,%3}, [%4];" \
        : "=r"((r)[0]), "=r"((r)[1]), "=r"((r)[2]), "=r"((r)[3]) : "r"(addr))
#define LDSM4T(r, addr) \
    asm volatile("ldmatrix.sync.aligned.m8n8.x4.trans.shared.b16 {%0,%1,%2,%3}, [%4];" \
        : "=r"((r)[0]), "=r"((r)[1]), "=r"((r)[2]), "=r"((r)[3]) : "r"(addr))

#define MMA16816(d, a, b0, b1) \
    asm volatile("mma.sync.aligned.m16n8k16.row.col.f32.f16.f16.f32 " \
        "{%0,%1,%2,%3}, {%4,%5,%6,%7}, {%8,%9}, {%0,%1,%2,%3};" \
        : "+f"((d)[0]), "+f"((d)[1]), "+f"((d)[2]), "+f"((d)[3]) \
        : "r"((a)[0]), "r"((a)[1]), "r"((a)[2]), "r"((a)[3]), "r"(b0), "r"(b1))

/* C = 0 variant (no accumulator read) */
#define MMA16816_INIT(d, a, b0, b1) \
    asm volatile("mma.sync.aligned.m16n8k16.row.col.f32.f16.f16.f32 " \
        "{%0,%1,%2,%3}, {%4,%5,%6,%7}, {%8,%9}, {%10,%10,%10,%10};" \
        : "=f"((d)[0]), "=f"((d)[1]), "=f"((d)[2]), "=f"((d)[3]) \
        : "r"((a)[0]), "r"((a)[1]), "r"((a)[2]), "r"((a)[3]), "r"(b0), "r"(b1), \
          "f"(0.f))

__device__ __forceinline__ uint32_t packh2(float x, float y) {
    __half2 h = __floats2half2_rn(x, y);
    return *(uint32_t*)&h;
}

// ---------------------------------------------------------------------------
// Fused prep kernel (one launch): W1^T, W2^T transpose-convert + query->fp16.
// ---------------------------------------------------------------------------
__global__ void prep_kernel(const float* __restrict__ query,
                            const float* __restrict__ w_qkv,
                            const float* __restrict__ w_o,
                            __half* __restrict__ A16,
                            __half* __restrict__ W1,
                            __half* __restrict__ W2)
{
    const int bid = blockIdx.x;
    const int tx = threadIdx.x, ty = threadIdx.y;

    if (bid < 4096) {
        const float* W;
        __half* T;
        int N, nb, b;
        if (bid < 3072) { W = w_qkv; T = W1; N = 3 * D_MODEL; nb = 96; b = bid; }
        else            { W = w_o;   T = W2; N = D_MODEL;     nb = 32; b = bid - 3072; }
        const int K = D_MODEL;
        const int n0 = (b % nb) * 32;
        const int k0 = (b / nb) * 32;
        __shared__ float t[32][33];
        #pragma unroll
        for (int i = ty; i < 32; i += 8)
            t[i][tx] = W[(size_t)(k0 + i) * N + n0 + tx];
        __syncthreads();
        #pragma unroll
        for (int i = ty; i < 32; i += 8)
            T[(size_t)(n0 + i) * K + k0 + tx] = __float2half_rn(t[tx][i]);
    } else {
        int i = (bid - 4096) * 256 + ty * 32 + tx;
        float4 v = ((const float4*)query)[i];
        *(uint2*)(A16 + (size_t)i * 4) =
            make_uint2(packh2(v.x, v.y), packh2(v.z, v.w));
    }
}

// ---------------------------------------------------------------------------
// HMMA fp16 GEMM (R10 config): C = A16[M,K] @ W[N,K]^T
// CTA 128x128, BK=64, 8 warps (2m x 4n), 3-stage cp.async, single barrier.
// ---------------------------------------------------------------------------
#define G_TILE   16384
#define G_STAGE  (2 * G_TILE)        /* 32768 */
#define GEMM_SMEM (3 * G_STAGE)      /* 98304 */

__device__ __forceinline__ void gemm_load(
    const __half* __restrict__ A, const __half* __restrict__ B,
    uint32_t sb, int m0, int n0, int K, int kofs, int tid)
{
    const int cr = tid >> 3;
    const int cc = tid & 7;
    const uint32_t csw = (uint32_t)((cc ^ (cr & 7)) << 4);
    #pragma unroll
    for (int u = 0; u < 4; u++) {
        int r = cr + u * 32;
        uint32_t so = (uint32_t)(r * 128) + csw;
        CP_ASYNC16(sb + so,          A + (size_t)(m0 + r) * K + kofs + cc * 8);
        CP_ASYNC16(sb + G_TILE + so, B + (size_t)(n0 + r) * K + kofs + cc * 8);
    }
    CP_COMMIT();
}

template <bool HALF_OUT>
__global__ void __launch_bounds__(256, 2) gemm_hmma_kernel(
    const __half* __restrict__ A16, const __half* __restrict__ B16,
    float* __restrict__ C, __half* __restrict__ Ch,
    int M, int N, int K)
{
    extern __shared__ char smem[];
    const uint32_t sbase = smem_u32(smem);
    const int tid = threadIdx.x;
    const int lid = tid & 31;
    const int wid = tid >> 5;
    const int wm  = wid >> 2;
    const int wn  = wid & 3;
    const int m0 = blockIdx.y * 128;
    const int n0 = blockIdx.x * 128;

    const int niter = K / 64;

    gemm_load(A16, B16, sbase,           m0, n0, K, 0,  tid);
    gemm_load(A16, B16, sbase + G_STAGE, m0, n0, K, 64, tid);

    float acc[4][4][4];
    #pragma unroll
    for (int i = 0; i < 4; i++)
        #pragma unroll
        for (int j = 0; j < 4; j++)
            #pragma unroll
            for (int k = 0; k < 4; k++) acc[i][j][k] = 0.f;

    const int a_rowlane = lid & 15;
    const int a_csel    = lid >> 4;
    const int b_rowlane = ((lid >> 4) << 3) + (lid & 7);
    const int b_csel    = (lid >> 3) & 1;
    const int sw_lane   = lid & 7;

    int stage = 0;
    for (int kt = 0; kt < niter; kt++) {
        if (kt + 1 < niter) { CP_WAIT1(); } else { CP_WAIT0(); }
        __syncthreads();   // data visible AND all warps done reading stage kt-1

        if (kt + 2 < niter) {
            int ps = stage + 2; if (ps >= 3) ps -= 3;
            gemm_load(A16, B16, sbase + ps * G_STAGE, m0, n0, K, (kt + 2) * 64, tid);
        } else {
            CP_COMMIT();
        }

        const uint32_t sb = sbase + stage * G_STAGE;
        const uint32_t abase0 = sb + (uint32_t)((wm * 64 + a_rowlane) * 128);
        const uint32_t bbase0 = sb + G_TILE + (uint32_t)((wn * 32 + b_rowlane) * 128);

        #pragma unroll
        for (int ks = 0; ks < 4; ks++) {
            const uint32_t abase = abase0 + (uint32_t)(((ks * 2 + a_csel) ^ sw_lane) << 4);
            const uint32_t bbase = bbase0 + (uint32_t)(((ks * 2 + b_csel) ^ sw_lane) << 4);

            uint32_t a[4][4], bb[2][4];
            #pragma unroll
            for (int tm = 0; tm < 4; tm++) LDSM4(a[tm], abase + tm * 2048);
            #pragma unroll
            for (int tg = 0; tg < 2; tg++) LDSM4(bb[tg], bbase + tg * 2048);

            #pragma unroll
            for (int tm = 0; tm < 4; tm++) {
                #pragma unroll
                for (int tg = 0; tg < 2; tg++) {
                    MMA16816(acc[tm][tg * 2 + 0], a[tm], bb[tg][0], bb[tg][1]);
                    MMA16816(acc[tm][tg * 2 + 1], a[tm], bb[tg][2], bb[tg][3]);
                }
            }
        }
        if (++stage == 3) stage = 0;
    }

    const int erow = (lid >> 2);
    const int ecol = (lid & 3) * 2;
    #pragma unroll
    for (int tm = 0; tm < 4; tm++) {
        #pragma unroll
        for (int tg = 0; tg < 4; tg++) {
            int row = m0 + wm * 64 + tm * 16 + erow;
            int col = n0 + wn * 32 + tg * 8 + ecol;
            if (HALF_OUT) {
                float f = (col < D_MODEL) ? QFAC : 1.f;  // bake SCALE*log2e into q
                *(uint32_t*)(Ch + (size_t)row * N + col) =
                    packh2(acc[tm][tg][0] * f, acc[tm][tg][1] * f);
                *(uint32_t*)(Ch + (size_t)(row + 8) * N + col) =
                    packh2(acc[tm][tg][2] * f, acc[tm][tg][3] * f);
            } else {
                *(float2*)(C + (size_t)row * N + col) =
                    make_float2(acc[tm][tg][0], acc[tm][tg][1]);
                *(float2*)(C + (size_t)(row + 8) * N + col) =
                    make_float2(acc[tm][tg][2], acc[tm][tg][3]);
            }
        }
    }
}

// ---------------------------------------------------------------------------
// HMMA flash attention (causal), fp16, software-pipelined (R13 structure):
// softmax(kt) -> wait/sync -> prefetch -> QK(kt+1) -> PV(kt).
// Softmax chain: fused f16x2 exp2, ones-MMA row sums.
// Grid TRANSPOSED: x = bh (32), y = q-tile reversed -> the 32 largest CTAs
// (qb=15) occupy bids 0..31 and start in wave 1 (LPT-style scheduling).
// 128 q-rows/CTA, 8 warps x m16, 4-stage KV ring. Q pre-scaled (log2 domain).
// ---------------------------------------------------------------------------
#define AQ    0
#define AKV0  (128 * 144)               /* 18432 */
#define KV_STAGE (2 * 64 * 144)         /* 18432 */
#define A_V   (64 * 144)
#define ATTN_SMEM (AKV0 + 4 * KV_STAGE) /* 92160 */

__device__ __forceinline__ void attn_load_kv(
    const __half* __restrict__ qkv, uint32_t dst, int grow0, int kcol, int tid)
{
    #pragma unroll
    for (int u = 0; u < 4; u++) {
        int piece = u >> 1;                       // 0:K 1:V
        int r = (u & 1) * 32 + (tid >> 3);
        int c = tid & 7;
        const __half* g = qkv + (size_t)(grow0 + r) * 3072 + kcol + piece * D_MODEL + c * 8;
        CP_ASYNC16(dst + piece * A_V + r * 144 + c * 16, g);
    }
    CP_COMMIT();
}

__global__ void __launch_bounds__(256, 2) attn_hmma_kernel(
    const __half* __restrict__ qkv, __half* __restrict__ ctx16)
{
    extern __shared__ char smem[];
    const uint32_t sbase = smem_u32(smem);
    const int tid = threadIdx.x;
    const int lid = tid & 31;
    const int wm  = tid >> 5;      // 0..7, warp covers rows wm*16..wm*16+15

    const int qb = (int)gridDim.y - 1 - (int)blockIdx.y;  // big tiles first
    const int bh = blockIdx.x;
    const int b  = bh >> 4;
    const int h  = bh & 15;
    const int q0 = qb * 128;
    const int nkt = qb * 2 + 2;    // >= 2

    const int qcol = h * D_K;
    const int browQ = b * SEQ + q0;
    const int kcol = D_MODEL + qcol;

    // --- Q loads (G0)
    #pragma unroll
    for (int u = 0; u < 4; u++) {
        int r = u * 32 + (tid >> 3);
        int c = tid & 7;
        CP_ASYNC16(sbase + AQ + r * 144 + c * 16,
                   qkv + (size_t)(browQ + r) * 3072 + qcol + c * 8);
    }
    CP_COMMIT();
    // --- KV tiles 0,1 (G1,G2); KV2 (G3, or empty commit)
    attn_load_kv(qkv, sbase + AKV0,            b * SEQ,      kcol, tid);
    attn_load_kv(qkv, sbase + AKV0 + KV_STAGE, b * SEQ + 64, kcol, tid);
    if (nkt > 2) {
        attn_load_kv(qkv, sbase + AKV0 + 2 * KV_STAGE, b * SEQ + 128, kcol, tid);
    } else {
        CP_COMMIT();
    }

    CP_WAIT2();            // Q + KV0 ready
    __syncthreads();

    // preload Q A-fragments (4 k-steps)
    const uint32_t q_addr = sbase + AQ + (uint32_t)((wm * 16 + (lid & 15)) * 144)
                            + (uint32_t)((lid >> 4) * 16);
    uint32_t aQ[4][4];
    #pragma unroll
    for (int ks = 0; ks < 4; ks++) LDSM4(aQ[ks], q_addr + ks * 32);

    const int b_row = ((lid >> 4) << 3) + (lid & 7);
    const int b_cs  = (lid >> 3) & 1;
    const int v_row = ((lid >> 3) & 1) * 8 + (lid & 7);
    const int v_col = (lid >> 4) * 8;
    const uint32_t ONES2 = 0x3C003C00u;   // half2(1,1)

    float O[8][4];
    #pragma unroll
    for (int t = 0; t < 8; t++)
        #pragma unroll
        for (int k = 0; k < 4; k++) O[t][k] = 0.f;
    float m0r = -1e30f, m1r = -1e30f, l0r = 0.f, l1r = 0.f;

    // ---- prologue: S(0) = QK(0)
    float S[8][4];
    #pragma unroll
    for (int t = 0; t < 8; t++)
        #pragma unroll
        for (int k = 0; k < 4; k++) S[t][k] = 0.f;
    {
        const uint32_t stg = sbase + AKV0;
        #pragma unroll
        for (int ks = 0; ks < 4; ks++) {
            const uint32_t kof = (uint32_t)((ks * 2 + b_cs) * 16);
            #pragma unroll
            for (int g = 0; g < 4; g++) {
                uint32_t kh[4];
                LDSM4(kh, stg + (uint32_t)((g * 16 + b_row) * 144) + kof);
                MMA16816(S[2 * g + 0], aQ[ks], kh[0], kh[1]);
                MMA16816(S[2 * g + 1], aQ[ks], kh[2], kh[3]);
            }
        }
    }

    const int row0 = q0 + wm * 16 + (lid >> 2);
    const int row1 = row0 + 8;
    const int wtop = q0 + wm * 16 + 15;   // highest q row in this warp

    for (int kt = 0; kt < nkt; kt++) {
        const int ktbase = kt * 64;
        const bool act_cur = (wtop >= ktbase);   // warp has any unmasked key
        uint32_t aP[4][4];

        if (act_cur) {
            // ---- softmax on S(kt) (log2 domain)
            const bool need_mask = (ktbase + 63) > row0;
            float vmax0 = -1e30f, vmax1 = -1e30f;
            #pragma unroll
            for (int t = 0; t < 8; t++) {
                float s0 = S[t][0], s1 = S[t][1], s2 = S[t][2], s3 = S[t][3];
                if (need_mask) {
                    int c0 = ktbase + t * 8 + (lid & 3) * 2;
                    if (c0     > row0) s0 = -1e9f;
                    if (c0 + 1 > row0) s1 = -1e9f;
                    if (c0     > row1) s2 = -1e9f;
                    if (c0 + 1 > row1) s3 = -1e9f;
                    S[t][0] = s0; S[t][1] = s1; S[t][2] = s2; S[t][3] = s3;
                }
                vmax0 = fmaxf(vmax0, fmaxf(s0, s1));
                vmax1 = fmaxf(vmax1, fmaxf(s2, s3));
            }
            vmax0 = fmaxf(vmax0, __shfl_xor_sync(0xffffffffu, vmax0, 1));
            vmax0 = fmaxf(vmax0, __shfl_xor_sync(0xffffffffu, vmax0, 2));
            vmax1 = fmaxf(vmax1, __shfl_xor_sync(0xffffffffu, vmax1, 1));
            vmax1 = fmaxf(vmax1, __shfl_xor_sync(0xffffffffu, vmax1, 2));

            const float mn0 = fmaxf(m0r, vmax0);
            const float mn1 = fmaxf(m1r, vmax1);
            const float a0 = ex2f(m0r - mn0);
            const float a1 = ex2f(m1r - mn1);
            m0r = mn0; m1r = mn1;

            // fused sub -> pack -> packed exp2 (output IS the P fragment)
            #pragma unroll
            for (int ks = 0; ks < 4; ks++) {
                aP[ks][0] = h2ex2(packh2(S[2 * ks][0] - mn0,     S[2 * ks][1] - mn0));
                aP[ks][1] = h2ex2(packh2(S[2 * ks][2] - mn1,     S[2 * ks][3] - mn1));
                aP[ks][2] = h2ex2(packh2(S[2 * ks + 1][0] - mn0, S[2 * ks + 1][1] - mn0));
                aP[ks][3] = h2ex2(packh2(S[2 * ks + 1][2] - mn1, S[2 * ks + 1][3] - mn1));
            }

            // row sums via ones-MMA: D[i][j] = sum_k P[i][k]  (cols identical)
            float ls[4];
            MMA16816_INIT(ls, aP[0], ONES2, ONES2);
            MMA16816(ls, aP[1], ONES2, ONES2);
            MMA16816(ls, aP[2], ONES2, ONES2);
            MMA16816(ls, aP[3], ONES2, ONES2);
            l0r = l0r * a0 + ls[0];
            l1r = l1r * a1 + ls[2];

            #pragma unroll
            for (int t = 0; t < 8; t++) {
                O[t][0] *= a0; O[t][1] *= a0;
                O[t][2] *= a1; O[t][3] *= a1;
            }
        }

        const bool more = (kt + 1 < nkt);
        if (more) CP_WAIT1();        // KV(kt+1) resident
        __syncthreads();             // all warps done reading stage kt-1

        // prefetch KV(kt+3) into stage (kt+3)&3
        if (kt + 3 < nkt) {
            attn_load_kv(qkv, sbase + AKV0 + ((kt + 3) & 3) * KV_STAGE,
                         b * SEQ + (kt + 3) * 64, kcol, tid);
        } else {
            CP_COMMIT();
        }

        // ---- QK(kt+1) -> S (skip if warp fully masked at kt+1)
        if (more && (wtop >= (kt + 1) * 64)) {
            #pragma unroll
            for (int t = 0; t < 8; t++)
                #pragma unroll
                for (int k = 0; k < 4; k++) S[t][k] = 0.f;
            const uint32_t stgn = sbase + AKV0 + ((kt + 1) & 3) * KV_STAGE;
            #pragma unroll
            for (int ks = 0; ks < 4; ks++) {
                const uint32_t kof = (uint32_t)((ks * 2 + b_cs) * 16);
                #pragma unroll
                for (int g = 0; g < 4; g++) {
                    uint32_t kh[4];
                    LDSM4(kh, stgn + (uint32_t)((g * 16 + b_row) * 144) + kof);
                    MMA16816(S[2 * g + 0], aQ[ks], kh[0], kh[1]);
                    MMA16816(S[2 * g + 1], aQ[ks], kh[2], kh[3]);
                }
            }
        }

        // ---- PV(kt) -> O (skip if warp fully masked at kt)
        if (act_cur) {
            const uint32_t stg = sbase + AKV0 + (kt & 3) * KV_STAGE;
            #pragma unroll
            for (int ks = 0; ks < 4; ks++) {
                #pragma unroll
                for (int g = 0; g < 4; g++) {
                    uint32_t vh[4];
                    LDSM4T(vh, stg + A_V + (uint32_t)((ks * 16 + v_row) * 144)
                               + (uint32_t)((v_col + g * 16) * 2));
                    MMA16816(O[2 * g + 0], aP[ks], vh[0], vh[1]);
                    MMA16816(O[2 * g + 1], aP[ks], vh[2], vh[3]);
                }
            }
        }
    }

    // ---- epilogue: normalize, fp16 pack, store ctx16 [4096,1024]
    const float inv0 = 1.f / l0r;
    const float inv1 = 1.f / l1r;
    const int gr0 = b * SEQ + row0;
    const int gr1 = b * SEQ + row1;
    #pragma unroll
    for (int t = 0; t < 8; t++) {
        int col = qcol + t * 8 + (lid & 3) * 2;
        *(uint32_t*)(ctx16 + (size_t)gr0 * D_MODEL + col) =
            packh2(O[t][0] * inv0, O[t][1] * inv0);
        *(uint32_t*)(ctx16 + (size_t)gr1 * D_MODEL + col) =
            packh2(O[t][2] * inv1, O[t][3] * inv1);
    }
}

// ---------------------------------------------------------------------------
extern "C" void kernel_launch(void* const* d_in, const int* in_sizes, int n_in,
                              void* d_out, int out_size)
{
    const float* query = (const float*)d_in[0];
    const float* w_qkv = (const float*)d_in[4];
    const float* w_o   = (const float*)d_in[5];
    float* out = (float*)d_out;

    __half *A16, *ctx16, *QKV, *W1, *W2;
    cudaGetSymbolAddress((void**)&A16,   g_A16);
    cudaGetSymbolAddress((void**)&ctx16, g_ctx16);
    cudaGetSymbolAddress((void**)&QKV,   g_QKV);
    cudaGetSymbolAddress((void**)&W1,    g_W1);
    cudaGetSymbolAddress((void**)&W2,    g_W2);

    cudaFuncSetAttribute(gemm_hmma_kernel<true>,
                         cudaFuncAttributeMaxDynamicSharedMemorySize, GEMM_SMEM);
    cudaFuncSetAttribute(gemm_hmma_kernel<false>,
                         cudaFuncAttributeMaxDynamicSharedMemorySize, GEMM_SMEM);
    cudaFuncSetAttribute(attn_hmma_kernel,
                         cudaFuncAttributeMaxDynamicSharedMemorySize, ATTN_SMEM);

    // 0) fused prep: W1^T, W2^T, query->fp16 in one launch
    prep_kernel<<<8192, dim3(32, 8)>>>(query, w_qkv, w_o, A16, W1, W2);

    // 1) qkv = query @ w_qkv -> fp16 (q columns pre-scaled by SCALE*log2e)
    gemm_hmma_kernel<true><<<dim3(3 * D_MODEL / 128, M_ROWS / 128), 256, GEMM_SMEM>>>(
        A16, W1, nullptr, QKV, M_ROWS, 3 * D_MODEL, D_MODEL);

    // 2) causal flash attention -> ctx fp16 (grid: x=bh, y=q-tile; big first)
    attn_hmma_kernel<<<dim3(BATCH * N_HEADS, SEQ / 128), 256, ATTN_SMEM>>>(
        QKV, ctx16);

    // 3) out = ctx @ w_o -> fp32
    gemm_hmma_kernel<false><<<dim3(D_MODEL / 128, M_ROWS / 128), 256, GEMM_SMEM>>>(
        ctx16, W2, out, nullptr, M_ROWS, D_MODEL, D_MODEL);
}